// round 3
// baseline (speedup 1.0000x reference)
#include <cuda_runtime.h>
#include <stdint.h>

#define NC    1000      // num classes
#define D4    256       // feature dim in float4 (1024 floats)
#define BQ    32768     // labels per batch (samples = 2*BQ rows of x)
#define MAXK  1024      // per-class index capacity (Poisson mean ~33)
#define CH    32        // samples per k_main block (equal-size chunks)
#define NBLK  (BQ / CH) // 1024 blocks

// ---- scratch (device globals; zero-initialized at module load; every replay
//      restores them to zero via the reset discipline below) ----
__device__ int   g_counts[NC];
__device__ int   g_idx[NC * MAXK];
__device__ int   g_flat[BQ];        // sample idx, sorted by class
__device__ int   g_flatc[BQ];       // class per flat position
__device__ int   g_off[NC + 1];     // class offsets into flat
__device__ float g_sum[NC * 1024];  // per-class partial sums (atomic target)
__device__ int   g_donecnt[NC];     // samples contributed per class
__device__ int   g_npresent;
__device__ int   g_sdone;
__device__ float g_loss;
__device__ int   g_clsdone;

// ---------------------------------------------------------------------------
// K1: counting-sort scatter + last-block compaction.
//  Label-width probe: reading int32 labels as int64 packs two labels; the
//  high word lands in [0,1000) with prob 1/1000 per pair, so 64 probes give
//  P(misdetect) ~ (1/1000)^64 ~ 0.
//  Last block (fence + done-counter) scans counts, emits the flat
//  class-sorted list + offsets, zeroes counts for the next graph replay.
// ---------------------------------------------------------------------------
__global__ void k_scatter(const int* __restrict__ l32,
                          const long long* __restrict__ l64) {
    __shared__ int sh_shift;
    __shared__ int s_last;
    const int t = threadIdx.x;
    if (t < 32) {
        int ok = 1;
        #pragma unroll
        for (int k = t; k < 64; k += 32) {
            long long v = l64[k];
            if (v < 0 || v >= NC) ok = 0;
        }
        unsigned m = __ballot_sync(0xffffffffu, ok);
        if (t == 0) sh_shift = (m == 0xffffffffu) ? 1 : 0;
    }
    __syncthreads();
    const int j = blockIdx.x * 1024 + t;          // 32 blocks * 1024 = 32768
    int c = l32[j << sh_shift];
    if ((unsigned)c < (unsigned)NC) {
        int p = atomicAdd(&g_counts[c], 1);
        if (p < MAXK) g_idx[c * MAXK + p] = j;
    }

    // ---- elect last block ----
    __syncthreads();
    if (t == 0) {
        __threadfence();
        s_last = (atomicAdd(&g_sdone, 1) == (int)gridDim.x - 1);
    }
    __syncthreads();
    if (!s_last) return;

    // ---- compaction (1024 threads) ----
    __shared__ int s_cnt[1024];
    __shared__ int s_inc[1024];
    int cc = (t < NC) ? g_counts[t] : 0;
    s_cnt[t] = cc;
    s_inc[t] = cc;
    if (t < NC) g_counts[t] = 0;                  // reset for next replay
    int np = __syncthreads_count(cc > 0);

    // Hillis-Steele inclusive scan over 1024
    #pragma unroll
    for (int o = 1; o < 1024; o <<= 1) {
        int v = s_inc[t];
        if (t >= o) v += s_inc[t - o];
        __syncthreads();
        s_inc[t] = v;
        __syncthreads();
    }
    if (t < NC) g_off[t] = s_inc[t] - s_cnt[t];
    if (t == 0) {
        g_off[NC] = s_inc[NC - 1];
        g_npresent = np;
        g_sdone = 0;                              // reset for next replay
    }
    __syncthreads();

    // copy class lists to flat (warp per class)
    const int w = t >> 5, lane = t & 31;
    for (int c2 = w; c2 < NC; c2 += 32) {
        int cnt = s_cnt[c2];
        if (cnt > MAXK) cnt = MAXK;
        int off = s_inc[c2] - s_cnt[c2];
        for (int i = lane; i < cnt; i += 32) {
            g_flat[off + i]  = g_idx[c2 * MAXK + i];
            g_flatc[off + i] = c2;
        }
    }
}

// ---------------------------------------------------------------------------
// K2: balanced main kernel. 1024 blocks x 128 threads, 32 samples per block
//     (equal work -> single perfectly-balanced wave, 8 blocks/SM).
//  Per class-run: register accumulation, RED.ADD into g_sum[class]; the
//  last contributor (per-class done counter) runs the fused epilogue:
//  mean + momentum EMA + L2 normalize + squared distance + loss atomic,
//  plus scratch reset. Last finished class writes the output scalar.
// ---------------------------------------------------------------------------
__global__ void __launch_bounds__(128, 8)
k_main(const float4* __restrict__ x4,
       const float4* __restrict__ ci4,
       const float4* __restrict__ cs4,
       float* __restrict__ out) {
    const int t = threadIdx.x;
    const int base = blockIdx.x * CH;
    __shared__ int   sj[CH];
    __shared__ int   scl[CH];
    __shared__ float sred[4];
    __shared__ int   sflag;

    const int tot = g_off[NC];
    int lim = tot - base;
    if (lim > CH) lim = CH;
    if (lim <= 0) return;

    if (t < CH && t < lim) {
        sj[t]  = g_flat[base + t];
        scl[t] = g_flatc[base + t];
    }
    __syncthreads();

    const float4* xa = x4 + t;          // float4 column t
    const float4* xb = x4 + t + 128;    // float4 column t+128

    int k = 0;
    while (k < lim) {
        const int c = scl[k];
        int e = k + 1;
        while (e < lim && scl[e] == c) e++;

        // ---- accumulate run [k, e) : 2 rows (crops) per sample ----
        float4 aA = make_float4(0.f,0.f,0.f,0.f);
        float4 bA = make_float4(0.f,0.f,0.f,0.f);
        float4 aB = make_float4(0.f,0.f,0.f,0.f);
        float4 bB = make_float4(0.f,0.f,0.f,0.f);
        int i = k;
        for (; i + 2 <= e; i += 2) {
            int j0 = sj[i], j1 = sj[i + 1];
            float4 p0 = __ldcs(xa + (size_t)j0 * D4);
            float4 q0 = __ldcs(xb + (size_t)j0 * D4);
            float4 p1 = __ldcs(xa + (size_t)(j0 + BQ) * D4);
            float4 q1 = __ldcs(xb + (size_t)(j0 + BQ) * D4);
            float4 p2 = __ldcs(xa + (size_t)j1 * D4);
            float4 q2 = __ldcs(xb + (size_t)j1 * D4);
            float4 p3 = __ldcs(xa + (size_t)(j1 + BQ) * D4);
            float4 q3 = __ldcs(xb + (size_t)(j1 + BQ) * D4);
            aA.x += p0.x + p1.x; aA.y += p0.y + p1.y; aA.z += p0.z + p1.z; aA.w += p0.w + p1.w;
            bA.x += q0.x + q1.x; bA.y += q0.y + q1.y; bA.z += q0.z + q1.z; bA.w += q0.w + q1.w;
            aB.x += p2.x + p3.x; aB.y += p2.y + p3.y; aB.z += p2.z + p3.z; aB.w += p2.w + p3.w;
            bB.x += q2.x + q3.x; bB.y += q2.y + q3.y; bB.z += q2.z + q3.z; bB.w += q2.w + q3.w;
        }
        if (i < e) {
            int j0 = sj[i];
            float4 p0 = __ldcs(xa + (size_t)j0 * D4);
            float4 q0 = __ldcs(xb + (size_t)j0 * D4);
            float4 p1 = __ldcs(xa + (size_t)(j0 + BQ) * D4);
            float4 q1 = __ldcs(xb + (size_t)(j0 + BQ) * D4);
            aA.x += p0.x + p1.x; aA.y += p0.y + p1.y; aA.z += p0.z + p1.z; aA.w += p0.w + p1.w;
            bA.x += q0.x + q1.x; bA.y += q0.y + q1.y; bA.z += q0.z + q1.z; bA.w += q0.w + q1.w;
        }
        aA.x += aB.x; aA.y += aB.y; aA.z += aB.z; aA.w += aB.w;
        bA.x += bB.x; bA.y += bB.y; bA.z += bB.z; bA.w += bB.w;

        // ---- contribute run to per-class global sum (RED.ADD, no return) ----
        float* gs = g_sum + (size_t)c * 1024;
        atomicAdd(gs + 4 * t + 0,   aA.x);
        atomicAdd(gs + 4 * t + 1,   aA.y);
        atomicAdd(gs + 4 * t + 2,   aA.z);
        atomicAdd(gs + 4 * t + 3,   aA.w);
        atomicAdd(gs + 4 * t + 512, bA.x);
        atomicAdd(gs + 4 * t + 513, bA.y);
        atomicAdd(gs + 4 * t + 514, bA.z);
        atomicAdd(gs + 4 * t + 515, bA.w);
        __threadfence();
        __syncthreads();
        if (t == 0) {
            int run = e - k;
            int cnt = g_off[c + 1] - g_off[c];
            int old = atomicAdd(&g_donecnt[c], run);
            sflag = (old + run == cnt);
        }
        __syncthreads();

        if (sflag) {
            // ---- this block completed class c: fused epilogue ----
            const int cnt = g_off[c + 1] - g_off[c];
            float4 sa = __ldcg((const float4*)gs + t);
            float4 sb = __ldcg((const float4*)gs + t + 128);
            ((float4*)gs)[t]       = make_float4(0.f,0.f,0.f,0.f);  // reset
            ((float4*)gs)[t + 128] = make_float4(0.f,0.f,0.f,0.f);
            if (t == 0) g_donecnt[c] = 0;

            const float s = 0.1f / (2.0f * (float)cnt);   // (1-mom)/count
            float4 cia = ci4[c * D4 + t];
            float4 cib = ci4[c * D4 + t + 128];
            float4 ua, ub;
            ua.x = cia.x * 0.9f + sa.x * s;  ua.y = cia.y * 0.9f + sa.y * s;
            ua.z = cia.z * 0.9f + sa.z * s;  ua.w = cia.w * 0.9f + sa.w * s;
            ub.x = cib.x * 0.9f + sb.x * s;  ub.y = cib.y * 0.9f + sb.y * s;
            ub.z = cib.z * 0.9f + sb.z * s;  ub.w = cib.w * 0.9f + sb.w * s;

            float nsq = ua.x*ua.x + ua.y*ua.y + ua.z*ua.z + ua.w*ua.w
                      + ub.x*ub.x + ub.y*ub.y + ub.z*ub.z + ub.w*ub.w;
            #pragma unroll
            for (int o = 16; o; o >>= 1) nsq += __shfl_down_sync(0xffffffffu, nsq, o);
            if ((t & 31) == 0) sred[t >> 5] = nsq;
            __syncthreads();
            float rnorm = rsqrtf(sred[0] + sred[1] + sred[2] + sred[3]);

            float4 csa = cs4[c * D4 + t];
            float4 csb = cs4[c * D4 + t + 128];
            float dx = ua.x * rnorm - csa.x, dy = ua.y * rnorm - csa.y;
            float dz = ua.z * rnorm - csa.z, dw = ua.w * rnorm - csa.w;
            float ls = dx*dx + dy*dy + dz*dz + dw*dw;
            dx = ub.x * rnorm - csb.x; dy = ub.y * rnorm - csb.y;
            dz = ub.z * rnorm - csb.z; dw = ub.w * rnorm - csb.w;
            ls += dx*dx + dy*dy + dz*dz + dw*dw;
            #pragma unroll
            for (int o = 16; o; o >>= 1) ls += __shfl_down_sync(0xffffffffu, ls, o);
            __syncthreads();                  // protect sred reuse
            if ((t & 31) == 0) sred[t >> 5] = ls;
            __syncthreads();

            if (t == 0) {
                atomicAdd(&g_loss, sred[0] + sred[1] + sred[2] + sred[3]);
                __threadfence();
                int oldc = atomicAdd(&g_clsdone, 1);
                if (oldc == g_npresent - 1) {
                    // last class finished anywhere on the chip: finalize
                    float L  = atomicAdd(&g_loss, 0.0f);   // coherent read
                    int   np = g_npresent;
                    out[0] = L / (float)(np > 0 ? np : 1);
                    g_loss = 0.0f;                          // reset for replay
                    g_clsdone = 0;
                }
            }
            __syncthreads();
        }
        k = e;
    }
}

extern "C" void kernel_launch(void* const* d_in, const int* in_sizes, int n_in,
                              void* d_out, int out_size) {
    const float4* x4  = (const float4*)d_in[0];
    const float4* ci4 = (const float4*)d_in[1];
    const float4* cs4 = (const float4*)d_in[2];
    const void*   l   = d_in[3];

    k_scatter<<<32, 1024>>>((const int*)l, (const long long*)l);
    k_main<<<NBLK, 128>>>(x4, ci4, cs4, (float*)d_out);
}

// round 7
// speedup vs baseline: 1.1635x; 1.1635x over previous
#include <cuda_runtime.h>
#include <stdint.h>

#define NC    1000      // num classes
#define D4    256       // feature dim in float4 (1024 floats)
#define BQ    32768     // labels per batch (samples = 2*BQ rows of x)
#define MAXK  1024      // per-class index capacity (Poisson mean ~33)
#define SPLIT 4         // parts per class
#define CAP   256       // per-part staging capacity (MAXK/SPLIT)

// ---- scratch (device globals; zero at load; reset discipline keeps them
//      zero across graph replays) ----
__device__ int   g_counts[NC];
__device__ int   g_idx[NC * MAXK];
__device__ float g_sum[NC * 1024];   // per-class combined sums (RED.ADD target)
__device__ int   g_done4[NC];        // parts finished per class
__device__ float g_loss;
__device__ int   g_present;
__device__ int   g_clsdone;

// ---------------------------------------------------------------------------
// K1: counting-sort scatter (R2-proven fast path) with label-width probe.
//  Reading int32 labels as int64 packs two labels; high word lands in
//  [0,1000) with prob 1/1000 per pair -> P(misdetect) ~ (1/1000)^64 ~ 0.
// ---------------------------------------------------------------------------
__global__ void k_scatter(const int* __restrict__ l32,
                          const long long* __restrict__ l64) {
    __shared__ int sh_shift;
    if (threadIdx.x < 32) {
        int ok = 1;
        #pragma unroll
        for (int k = threadIdx.x; k < 64; k += 32) {
            long long v = l64[k];
            if (v < 0 || v >= NC) ok = 0;
        }
        unsigned m = __ballot_sync(0xffffffffu, ok);
        if (threadIdx.x == 0) sh_shift = (m == 0xffffffffu) ? 1 : 0;
    }
    __syncthreads();
    const int shift = sh_shift;           // 1 => int64: low word at index 2*j
    int stride = gridDim.x * blockDim.x;
    for (int j = blockIdx.x * blockDim.x + threadIdx.x; j < BQ; j += stride) {
        int c = l32[j << shift];
        if ((unsigned)c < (unsigned)NC) {
            int pos = atomicAdd(&g_counts[c], 1);
            if (pos < MAXK) g_idx[c * MAXK + pos] = j;
        }
    }
}

// ---------------------------------------------------------------------------
// K2: main kernel. SPLIT blocks per class (4000 blocks x 128 threads).
//  Hot loop: pure register accumulation, 8 independent LDG.128 in flight
//  per thread. One batch of RED.ADDs + fence AFTER the loop. The 4th
//  finisher of each class runs the fused epilogue; the last class writes out.
// ---------------------------------------------------------------------------
__global__ void __launch_bounds__(128, 8)
k_main(const float4* __restrict__ x4,
       const float4* __restrict__ ci4,
       const float4* __restrict__ cs4,
       float* __restrict__ out) {
    const int c    = blockIdx.x >> 2;
    const int part = blockIdx.x & 3;
    const int t    = threadIdx.x;
    __shared__ int   sidx[CAP];
    __shared__ float sred[4];
    __shared__ int   sflag;

    int cnt = g_counts[c];
    if (cnt > MAXK) cnt = MAXK;           // defensive (statistically impossible)

    // this part's slice [lo, hi)
    const int lo = (cnt * part)       / SPLIT;
    const int hi = (cnt * (part + 1)) / SPLIT;
    const int n  = hi - lo;

    if (n > 0) {
        for (int k = t; k < n; k += 128) sidx[k] = g_idx[c * MAXK + lo + k];
        __syncthreads();

        const float4* xa = x4 + t;          // float4 column t
        const float4* xb = x4 + t + 128;    // float4 column t+128
        float4 aA = make_float4(0.f,0.f,0.f,0.f);
        float4 bA = make_float4(0.f,0.f,0.f,0.f);
        float4 aB = make_float4(0.f,0.f,0.f,0.f);
        float4 bB = make_float4(0.f,0.f,0.f,0.f);

        int k = 0;
        for (; k + 2 <= n; k += 2) {
            int j0 = sidx[k], j1 = sidx[k + 1];
            float4 p0 = __ldcs(xa + (size_t)j0 * D4);
            float4 q0 = __ldcs(xb + (size_t)j0 * D4);
            float4 p1 = __ldcs(xa + (size_t)(j0 + BQ) * D4);
            float4 q1 = __ldcs(xb + (size_t)(j0 + BQ) * D4);
            float4 p2 = __ldcs(xa + (size_t)j1 * D4);
            float4 q2 = __ldcs(xb + (size_t)j1 * D4);
            float4 p3 = __ldcs(xa + (size_t)(j1 + BQ) * D4);
            float4 q3 = __ldcs(xb + (size_t)(j1 + BQ) * D4);
            aA.x += p0.x + p1.x; aA.y += p0.y + p1.y; aA.z += p0.z + p1.z; aA.w += p0.w + p1.w;
            bA.x += q0.x + q1.x; bA.y += q0.y + q1.y; bA.z += q0.z + q1.z; bA.w += q0.w + q1.w;
            aB.x += p2.x + p3.x; aB.y += p2.y + p3.y; aB.z += p2.z + p3.z; aB.w += p2.w + p3.w;
            bB.x += q2.x + q3.x; bB.y += q2.y + q3.y; bB.z += q2.z + q3.z; bB.w += q2.w + q3.w;
        }
        if (k < n) {
            int j0 = sidx[k];
            float4 p0 = __ldcs(xa + (size_t)j0 * D4);
            float4 q0 = __ldcs(xb + (size_t)j0 * D4);
            float4 p1 = __ldcs(xa + (size_t)(j0 + BQ) * D4);
            float4 q1 = __ldcs(xb + (size_t)(j0 + BQ) * D4);
            aA.x += p0.x + p1.x; aA.y += p0.y + p1.y; aA.z += p0.z + p1.z; aA.w += p0.w + p1.w;
            bA.x += q0.x + q1.x; bA.y += q0.y + q1.y; bA.z += q0.z + q1.z; bA.w += q0.w + q1.w;
        }
        aA.x += aB.x; aA.y += aB.y; aA.z += aB.z; aA.w += aB.w;
        bA.x += bB.x; bA.y += bB.y; bA.z += bB.z; bA.w += bB.w;

        // one batch of RED.ADDs (fire-and-forget), fenced once below
        float* gs = g_sum + (size_t)c * 1024;
        atomicAdd(gs + 4 * t + 0,   aA.x);
        atomicAdd(gs + 4 * t + 1,   aA.y);
        atomicAdd(gs + 4 * t + 2,   aA.z);
        atomicAdd(gs + 4 * t + 3,   aA.w);
        atomicAdd(gs + 4 * t + 512, bA.x);
        atomicAdd(gs + 4 * t + 513, bA.y);
        atomicAdd(gs + 4 * t + 514, bA.z);
        atomicAdd(gs + 4 * t + 515, bA.w);
    }

    // ---- elect 4th finisher of this class ----
    __syncthreads();
    if (t == 0) {
        __threadfence();
        sflag = (atomicAdd(&g_done4[c], 1) == SPLIT - 1);
    }
    __syncthreads();
    if (!sflag) return;
    if (t == 0) { g_done4[c] = 0; g_counts[c] = 0; }   // resets for replay

    if (cnt > 0) {
        // ---- fused epilogue: mean + EMA + normalize + loss ----
        float* gs = g_sum + (size_t)c * 1024;
        float4 sa = __ldcg((const float4*)gs + t);
        float4 sb = __ldcg((const float4*)gs + t + 128);
        ((float4*)gs)[t]       = make_float4(0.f,0.f,0.f,0.f);  // reset
        ((float4*)gs)[t + 128] = make_float4(0.f,0.f,0.f,0.f);

        const float s = 0.1f / (2.0f * (float)cnt);    // (1-mom)/count
        float4 cia = ci4[c * D4 + t];
        float4 cib = ci4[c * D4 + t + 128];
        float4 ua, ub;
        ua.x = cia.x * 0.9f + sa.x * s;  ua.y = cia.y * 0.9f + sa.y * s;
        ua.z = cia.z * 0.9f + sa.z * s;  ua.w = cia.w * 0.9f + sa.w * s;
        ub.x = cib.x * 0.9f + sb.x * s;  ub.y = cib.y * 0.9f + sb.y * s;
        ub.z = cib.z * 0.9f + sb.z * s;  ub.w = cib.w * 0.9f + sb.w * s;

        float nsq = ua.x*ua.x + ua.y*ua.y + ua.z*ua.z + ua.w*ua.w
                  + ub.x*ub.x + ub.y*ub.y + ub.z*ub.z + ub.w*ub.w;
        #pragma unroll
        for (int o = 16; o; o >>= 1) nsq += __shfl_down_sync(0xffffffffu, nsq, o);
        if ((t & 31) == 0) sred[t >> 5] = nsq;
        __syncthreads();
        float rnorm = rsqrtf(sred[0] + sred[1] + sred[2] + sred[3]);

        float4 csa = cs4[c * D4 + t];
        float4 csb = cs4[c * D4 + t + 128];
        float dx = ua.x * rnorm - csa.x, dy = ua.y * rnorm - csa.y;
        float dz = ua.z * rnorm - csa.z, dw = ua.w * rnorm - csa.w;
        float ls = dx*dx + dy*dy + dz*dz + dw*dw;
        dx = ub.x * rnorm - csb.x; dy = ub.y * rnorm - csb.y;
        dz = ub.z * rnorm - csb.z; dw = ub.w * rnorm - csb.w;
        ls += dx*dx + dy*dy + dz*dz + dw*dw;
        #pragma unroll
        for (int o = 16; o; o >>= 1) ls += __shfl_down_sync(0xffffffffu, ls, o);
        __syncthreads();                  // protect sred reuse
        if ((t & 31) == 0) sred[t >> 5] = ls;
        __syncthreads();
        if (t == 0) {
            atomicAdd(&g_loss, sred[0] + sred[1] + sred[2] + sred[3]);
            atomicAdd(&g_present, 1);
        }
    }

    // ---- chip-level completion: one increment per class ----
    if (t == 0) {
        __threadfence();
        if (atomicAdd(&g_clsdone, 1) == NC - 1) {
            float L  = atomicAdd(&g_loss, 0.0f);       // L2-coherent read
            int   np = atomicAdd(&g_present, 0);
            out[0] = L / (float)(np > 0 ? np : 1);
            g_loss = 0.0f; g_present = 0; g_clsdone = 0;  // reset for replay
            __threadfence();
        }
    }
}

extern "C" void kernel_launch(void* const* d_in, const int* in_sizes, int n_in,
                              void* d_out, int out_size) {
    const float4* x4  = (const float4*)d_in[0];
    const float4* ci4 = (const float4*)d_in[1];
    const float4* cs4 = (const float4*)d_in[2];
    const void*   l   = d_in[3];

    k_scatter<<<64, 512>>>((const int*)l, (const long long*)l);
    k_main<<<NC * SPLIT, 128>>>(x4, ci4, cs4, (float*)d_out);
}

// round 8
// speedup vs baseline: 1.2831x; 1.1028x over previous
#include <cuda_runtime.h>
#include <stdint.h>

#define NC    1000      // num classes
#define D4    256       // feature dim in float4 (1024 floats)
#define BQ    32768     // labels per batch (samples = 2*BQ rows of x)
#define MAXK  1024      // per-class index capacity (Poisson mean ~33)
#define CH    32        // samples per k_main block
#define NBLK  (BQ / CH) // 1024 blocks
#define MAXR  8         // max class-runs a 32-sample chunk can straddle

// ---- scratch (device globals; zero at load; reset discipline below) ----
__device__ int   g_counts[NC];
__device__ int   g_idx[NC * MAXK];
__device__ int   g_off[NC + 1];      // exclusive scan of counts
__device__ float g_sum[NC * 1024];   // per-class sums (RED.ADD target)
__device__ int   g_donec[NC];        // samples contributed per class
__device__ int   g_npresent;
__device__ int   g_sdone;
__device__ float g_loss;
__device__ int   g_clsdone;

// ---------------------------------------------------------------------------
// K1: counting-sort scatter (R2-proven) + last-block 1000-elem scan.
//  Label-width probe: reading int32 labels as int64 packs two labels; the
//  high word lands in [0,1000) with prob 1/1000 per pair -> P(misdetect)~0.
// ---------------------------------------------------------------------------
__global__ void k_scatter(const int* __restrict__ l32,
                          const long long* __restrict__ l64) {
    __shared__ int sh_shift;
    __shared__ int s_last;
    const int t = threadIdx.x;
    if (t < 32) {
        int ok = 1;
        #pragma unroll
        for (int k = t; k < 64; k += 32) {
            long long v = l64[k];
            if (v < 0 || v >= NC) ok = 0;
        }
        unsigned m = __ballot_sync(0xffffffffu, ok);
        if (t == 0) sh_shift = (m == 0xffffffffu) ? 1 : 0;
    }
    __syncthreads();
    const int shift = sh_shift;
    const int j = blockIdx.x * 1024 + t;      // 32 blocks x 1024 threads
    int c = l32[j << shift];
    if ((unsigned)c < (unsigned)NC) {
        int pos = atomicAdd(&g_counts[c], 1);
        if (pos < MAXK) g_idx[c * MAXK + pos] = j;
    }

    // ---- last block does the scan (cheap: 10 iters over 1024) ----
    __syncthreads();
    if (t == 0) {
        __threadfence();
        s_last = (atomicAdd(&g_sdone, 1) == (int)gridDim.x - 1);
    }
    __syncthreads();
    if (!s_last) return;

    __shared__ int s_inc[1024];
    int cc = (t < NC) ? g_counts[t] : 0;
    if (t < NC) g_counts[t] = 0;              // reset for next replay
    int np = __syncthreads_count(cc > 0);
    s_inc[t] = cc;
    __syncthreads();
    #pragma unroll
    for (int o = 1; o < 1024; o <<= 1) {
        int v = s_inc[t];
        if (t >= o) v += s_inc[t - o];
        __syncthreads();
        s_inc[t] = v;
        __syncthreads();
    }
    if (t < NC) g_off[t] = s_inc[t] - cc;
    if (t == 0) {
        g_off[NC] = s_inc[NC - 1];
        g_npresent = np;
        g_sdone = 0;
    }
}

// ---------------------------------------------------------------------------
// epilogue for a completed class (R4-proven): mean + EMA + normalize + loss
// ---------------------------------------------------------------------------
__device__ __forceinline__ void class_epilogue(
        int c, int cnt, int t,
        const float4* __restrict__ ci4, const float4* __restrict__ cs4,
        float* __restrict__ out, float* sred) {
    float* gs = g_sum + (size_t)c * 1024;
    float4 sa = __ldcg((const float4*)gs + t);
    float4 sb = __ldcg((const float4*)gs + t + 128);
    ((float4*)gs)[t]       = make_float4(0.f,0.f,0.f,0.f);  // reset for replay
    ((float4*)gs)[t + 128] = make_float4(0.f,0.f,0.f,0.f);

    const float s = 0.1f / (2.0f * (float)cnt);
    float4 cia = ci4[c * D4 + t];
    float4 cib = ci4[c * D4 + t + 128];
    float4 ua, ub;
    ua.x = cia.x * 0.9f + sa.x * s;  ua.y = cia.y * 0.9f + sa.y * s;
    ua.z = cia.z * 0.9f + sa.z * s;  ua.w = cia.w * 0.9f + sa.w * s;
    ub.x = cib.x * 0.9f + sb.x * s;  ub.y = cib.y * 0.9f + sb.y * s;
    ub.z = cib.z * 0.9f + sb.z * s;  ub.w = cib.w * 0.9f + sb.w * s;

    float nsq = ua.x*ua.x + ua.y*ua.y + ua.z*ua.z + ua.w*ua.w
              + ub.x*ub.x + ub.y*ub.y + ub.z*ub.z + ub.w*ub.w;
    #pragma unroll
    for (int o = 16; o; o >>= 1) nsq += __shfl_down_sync(0xffffffffu, nsq, o);
    if ((t & 31) == 0) sred[t >> 5] = nsq;
    __syncthreads();
    float rnorm = rsqrtf(sred[0] + sred[1] + sred[2] + sred[3]);

    float4 csa = cs4[c * D4 + t];
    float4 csb = cs4[c * D4 + t + 128];
    float dx = ua.x * rnorm - csa.x, dy = ua.y * rnorm - csa.y;
    float dz = ua.z * rnorm - csa.z, dw = ua.w * rnorm - csa.w;
    float ls = dx*dx + dy*dy + dz*dz + dw*dw;
    dx = ub.x * rnorm - csb.x; dy = ub.y * rnorm - csb.y;
    dz = ub.z * rnorm - csb.z; dw = ub.w * rnorm - csb.w;
    ls += dx*dx + dy*dy + dz*dz + dw*dw;
    #pragma unroll
    for (int o = 16; o; o >>= 1) ls += __shfl_down_sync(0xffffffffu, ls, o);
    __syncthreads();                  // protect sred reuse
    if ((t & 31) == 0) sred[t >> 5] = ls;
    __syncthreads();

    if (t == 0) {
        atomicAdd(&g_loss, sred[0] + sred[1] + sred[2] + sred[3]);
        __threadfence();
        if (atomicAdd(&g_clsdone, 1) == g_npresent - 1) {
            float L = atomicAdd(&g_loss, 0.0f);       // L2-coherent read
            int  np = g_npresent;
            out[0] = L / (float)(np > 0 ? np : 1);
            g_loss = 0.0f; g_clsdone = 0;             // reset for replay
            __threadfence();
        }
    }
    __syncthreads();
}

// ---------------------------------------------------------------------------
// K2: balanced main kernel. 1024 blocks x 128 threads, exactly 32 samples
//  each (single perfectly-balanced wave). Hot loop is fence-free: per class
//  run -> register accumulation -> one batch of RED.ADDs -> next run.
//  All synchronization deferred to after the last load.
// ---------------------------------------------------------------------------
__global__ void __launch_bounds__(128, 8)
k_main(const float4* __restrict__ x4,
       const float4* __restrict__ ci4,
       const float4* __restrict__ cs4,
       float* __restrict__ out) {
    const int t    = threadIdx.x;
    const int base = blockIdx.x * CH;
    __shared__ int   sidx[CH];
    __shared__ float sred[4];
    __shared__ int   scls[MAXR];
    __shared__ int   srun[MAXR];
    __shared__ int   sdo[MAXR];

    const int total = g_off[NC];
    int end = base + CH;
    if (end > total) end = total;
    if (base >= end) return;

    // find first class: largest c with g_off[c] <= base (binary search)
    int lo_s = 0, hi_s = NC;
    while (lo_s < hi_s) {                 // invariant: off[lo_s] <= base < off[hi_s+? ]
        int mid = (lo_s + hi_s + 1) >> 1;
        if (g_off[mid] <= base) lo_s = mid; else hi_s = mid - 1;
    }
    int c = lo_s;

    const float4* xa = x4 + t;            // float4 column t
    const float4* xb = x4 + t + 128;      // float4 column t+128

    int pos = base;
    int m = 0;                            // number of runs handled
    while (pos < end) {
        while (g_off[c + 1] <= pos) c++;  // advance to class containing pos
        int rend = g_off[c + 1];
        if (rend > end) rend = end;
        const int n = rend - pos;         // run length (1..32)

        // stage this run's indices
        if (t < n) sidx[t] = g_idx[c * MAXK + (pos - g_off[c]) + t];
        __syncthreads();

        // ---- register accumulation (8 independent LDG.128 in flight) ----
        float4 aA = make_float4(0.f,0.f,0.f,0.f);
        float4 bA = make_float4(0.f,0.f,0.f,0.f);
        float4 aB = make_float4(0.f,0.f,0.f,0.f);
        float4 bB = make_float4(0.f,0.f,0.f,0.f);
        int k = 0;
        for (; k + 2 <= n; k += 2) {
            int j0 = sidx[k], j1 = sidx[k + 1];
            float4 p0 = __ldcs(xa + (size_t)j0 * D4);
            float4 q0 = __ldcs(xb + (size_t)j0 * D4);
            float4 p1 = __ldcs(xa + (size_t)(j0 + BQ) * D4);
            float4 q1 = __ldcs(xb + (size_t)(j0 + BQ) * D4);
            float4 p2 = __ldcs(xa + (size_t)j1 * D4);
            float4 q2 = __ldcs(xb + (size_t)j1 * D4);
            float4 p3 = __ldcs(xa + (size_t)(j1 + BQ) * D4);
            float4 q3 = __ldcs(xb + (size_t)(j1 + BQ) * D4);
            aA.x += p0.x + p1.x; aA.y += p0.y + p1.y; aA.z += p0.z + p1.z; aA.w += p0.w + p1.w;
            bA.x += q0.x + q1.x; bA.y += q0.y + q1.y; bA.z += q0.z + q1.z; bA.w += q0.w + q1.w;
            aB.x += p2.x + p3.x; aB.y += p2.y + p3.y; aB.z += p2.z + p3.z; aB.w += p2.w + p3.w;
            bB.x += q2.x + q3.x; bB.y += q2.y + q3.y; bB.z += q2.z + q3.z; bB.w += q2.w + q3.w;
        }
        if (k < n) {
            int j0 = sidx[k];
            float4 p0 = __ldcs(xa + (size_t)j0 * D4);
            float4 q0 = __ldcs(xb + (size_t)j0 * D4);
            float4 p1 = __ldcs(xa + (size_t)(j0 + BQ) * D4);
            float4 q1 = __ldcs(xb + (size_t)(j0 + BQ) * D4);
            aA.x += p0.x + p1.x; aA.y += p0.y + p1.y; aA.z += p0.z + p1.z; aA.w += p0.w + p1.w;
            bA.x += q0.x + q1.x; bA.y += q0.y + q1.y; bA.z += q0.z + q1.z; bA.w += q0.w + q1.w;
        }
        aA.x += aB.x; aA.y += aB.y; aA.z += aB.z; aA.w += aB.w;
        bA.x += bB.x; bA.y += bB.y; bA.z += bB.z; bA.w += bB.w;

        // fire-and-forget RED.ADDs (no fence here)
        float* gs = g_sum + (size_t)c * 1024;
        atomicAdd(gs + 4 * t + 0,   aA.x);
        atomicAdd(gs + 4 * t + 1,   aA.y);
        atomicAdd(gs + 4 * t + 2,   aA.z);
        atomicAdd(gs + 4 * t + 3,   aA.w);
        atomicAdd(gs + 4 * t + 512, bA.x);
        atomicAdd(gs + 4 * t + 513, bA.y);
        atomicAdd(gs + 4 * t + 514, bA.z);
        atomicAdd(gs + 4 * t + 515, bA.w);

        if (t == 0 && m < MAXR) { scls[m] = c; srun[m] = n; }
        m++;
        __syncthreads();                  // sidx reuse (no global fence)
        pos = rend;
    }
    if (m > MAXR) m = MAXR;

    // ---- deferred completion protocol (once per block) ----
    __threadfence();
    __syncthreads();
    if (t == 0) {
        for (int r = 0; r < m; r++) {
            int cc  = scls[r];
            int cnt = g_off[cc + 1] - g_off[cc];
            int old = atomicAdd(&g_donec[cc], srun[r]);
            sdo[r] = (old + srun[r] == cnt);
            if (sdo[r]) g_donec[cc] = 0;          // reset for replay
        }
    }
    __syncthreads();

    for (int r = 0; r < m; r++) {
        if (sdo[r]) {
            int cc  = scls[r];
            int cnt = g_off[cc + 1] - g_off[cc];
            class_epilogue(cc, cnt, t, ci4, cs4, out, sred);
        }
    }
}

extern "C" void kernel_launch(void* const* d_in, const int* in_sizes, int n_in,
                              void* d_out, int out_size) {
    const float4* x4  = (const float4*)d_in[0];
    const float4* ci4 = (const float4*)d_in[1];
    const float4* cs4 = (const float4*)d_in[2];
    const void*   l   = d_in[3];

    k_scatter<<<32, 1024>>>((const int*)l, (const long long*)l);
    k_main<<<NBLK, 128>>>(x4, ci4, cs4, (float*)d_out);
}